// round 2
// baseline (speedup 1.0000x reference)
#include <cuda_runtime.h>

#define Hdim 1024
#define Wdim 1024
#define HWdim (Hdim * Wdim)
#define TS 32
#define NT 256

// Folded MLP: M[2][6] = lw2 @ lw1, B[2] = lw2 @ lb1 + lb2
__device__ float g_M[12];
__device__ float g_B[2];

__global__ void fold_mlp_kernel(const float* __restrict__ lw1,
                                const float* __restrict__ lb1,
                                const float* __restrict__ lw2,
                                const float* __restrict__ lb2) {
    int t = threadIdx.x;
    if (t < 12) {
        int o = t / 6, c = t % 6;
        float acc = 0.0f;
        for (int k = 0; k < 128; k++)
            acc += lw2[o * 128 + k] * lw1[k * 6 + c];
        g_M[t] = acc;
    } else if (t < 14) {
        int o = t - 12;
        float acc = lb2[o];
        for (int k = 0; k < 128; k++)
            acc += lw2[o * 128 + k] * lb1[k];
        g_B[o] = acc;
    }
}

__device__ __forceinline__ float sigmoidf_(float y) {
    return 1.0f / (1.0f + __expf(-y));
}

__global__ __launch_bounds__(NT) void unet_fused_kernel(
    const float* __restrict__ x,  const float* __restrict__ x2,
    const float* __restrict__ w1a, const float* __restrict__ b1a,
    const float* __restrict__ w2a, const float* __restrict__ b2a,
    const float* __restrict__ w3a, const float* __restrict__ b3a,
    const float* __restrict__ w1b, const float* __restrict__ b1b,
    const float* __restrict__ w2b, const float* __restrict__ b2b,
    const float* __restrict__ w3b, const float* __restrict__ b3b,
    float* __restrict__ outf, float* __restrict__ den1, float* __restrict__ den2)
{
    __shared__ float s_x[3][38][38];   // input tile with 3-halo
    __shared__ float s_c4[36][36];     // conv1 output (2-halo)
    __shared__ float s_c5[34][34];     // conv2 output (1-halo)
    __shared__ float s_w[108];         // w1(27) | w2(36) | w3(45)
    __shared__ float s_b[3];
    __shared__ float s_M[12];
    __shared__ float s_B2[2];

    const int tid = threadIdx.x;
    const int h0  = blockIdx.y * TS;
    const int w0  = blockIdx.x * TS;

    if (tid < 12) s_M[tid] = g_M[tid];
    if (tid < 2)  s_B2[tid] = g_B[tid];

    float fa[4][6];  // encoder-a feature vectors for this thread's 4 pixels

    #pragma unroll 1
    for (int e = 0; e < 2; e++) {
        const float* X  = e ? x2  : x;
        const float* W1 = e ? w1b : w1a;
        const float* W2 = e ? w2b : w2a;
        const float* W3 = e ? w3b : w3a;
        const float* B1 = e ? b1b : b1a;
        const float* Bc2 = e ? b2b : b2a;
        const float* B3 = e ? b3b : b3a;
        float* den = e ? den2 : den1;

        // protect smem reuse across encoder iterations
        __syncthreads();

        // ---- load weights ----
        if (tid < 108) {
            float v;
            if (tid < 27)      v = W1[tid];
            else if (tid < 63) v = W2[tid - 27];
            else               v = W3[tid - 63];
            s_w[tid] = v;
        }
        if (tid == 120) s_b[0] = B1[0];
        if (tid == 121) s_b[1] = Bc2[0];
        if (tid == 122) s_b[2] = B3[0];

        // ---- load input tile (3 channels, 3-halo, zero padded) ----
        #pragma unroll 1
        for (int idx = tid; idx < 3 * 38 * 38; idx += NT) {
            int c = idx / (38 * 38);
            int rem = idx - c * (38 * 38);
            int r = rem / 38;
            int q = rem - r * 38;
            int gh = h0 - 3 + r, gw = w0 - 3 + q;
            float v = 0.0f;
            if ((unsigned)gh < Hdim && (unsigned)gw < Wdim)
                v = X[c * HWdim + gh * Wdim + gw];
            s_x[c][r][q] = v;
        }
        __syncthreads();

        // ---- conv1: 3ch -> c4, over 36x36 (2-halo) ----
        // IMPORTANT: positions outside the image must be 0 (the reference's
        // SAME padding zero-pads the concatenated tensor, so the conv1
        // channel is zero outside the image, not sigmoid(conv(zeropad))).
        #pragma unroll 1
        for (int idx = tid; idx < 36 * 36; idx += NT) {
            int j = idx / 36, i = idx - (idx / 36) * 36;
            float acc = s_b[0];
            #pragma unroll
            for (int c = 0; c < 3; c++)
                #pragma unroll
                for (int kh = 0; kh < 3; kh++)
                    #pragma unroll
                    for (int kw = 0; kw < 3; kw++)
                        acc += s_w[c * 9 + kh * 3 + kw] * s_x[c][j + kh][i + kw];
            int gh = h0 + j - 2, gw = w0 + i - 2;
            bool in_img = (unsigned)gh < Hdim && (unsigned)gw < Wdim;
            s_c4[j][i] = in_img ? sigmoidf_(acc) : 0.0f;
        }
        __syncthreads();

        // ---- conv2: [x(3), c4] -> c5, over 34x34 (1-halo) ----
        #pragma unroll 1
        for (int idx = tid; idx < 34 * 34; idx += NT) {
            int j = idx / 34, i = idx - (idx / 34) * 34;
            float acc = s_b[1];
            #pragma unroll
            for (int c = 0; c < 3; c++)
                #pragma unroll
                for (int kh = 0; kh < 3; kh++)
                    #pragma unroll
                    for (int kw = 0; kw < 3; kw++)
                        acc += s_w[27 + c * 9 + kh * 3 + kw] * s_x[c][j + 1 + kh][i + 1 + kw];
            #pragma unroll
            for (int kh = 0; kh < 3; kh++)
                #pragma unroll
                for (int kw = 0; kw < 3; kw++)
                    acc += s_w[27 + 27 + kh * 3 + kw] * s_c4[j + kh][i + kw];
            int gh = h0 + j - 1, gw = w0 + i - 1;
            bool in_img = (unsigned)gh < Hdim && (unsigned)gw < Wdim;
            s_c5[j][i] = in_img ? sigmoidf_(acc) : 0.0f;
        }
        __syncthreads();

        // ---- conv3: [x(3), c4, c5] -> c6, plus outputs, over 32x32 ----
        #pragma unroll
        for (int k = 0; k < (TS * TS) / NT; k++) {
            int p = tid + k * NT;
            int j = p >> 5, i = p & 31;
            float acc = s_b[2];
            #pragma unroll
            for (int c = 0; c < 3; c++)
                #pragma unroll
                for (int kh = 0; kh < 3; kh++)
                    #pragma unroll
                    for (int kw = 0; kw < 3; kw++)
                        acc += s_w[63 + c * 9 + kh * 3 + kw] * s_x[c][j + 2 + kh][i + 2 + kw];
            #pragma unroll
            for (int kh = 0; kh < 3; kh++)
                #pragma unroll
                for (int kw = 0; kw < 3; kw++)
                    acc += s_w[63 + 27 + kh * 3 + kw] * s_c4[j + 1 + kh][i + 1 + kw];
            #pragma unroll
            for (int kh = 0; kh < 3; kh++)
                #pragma unroll
                for (int kw = 0; kw < 3; kw++)
                    acc += s_w[63 + 36 + kh * 3 + kw] * s_c5[j + kh][i + kw];
            float f5 = sigmoidf_(acc);

            float f0 = s_x[0][j + 3][i + 3];
            float f1 = s_x[1][j + 3][i + 3];
            float f2 = s_x[2][j + 3][i + 3];
            float f3 = s_c4[j + 2][i + 2];
            float f4 = s_c5[j + 1][i + 1];

            int pix = (h0 + j) * Wdim + (w0 + i);
            // HWC write: 6 contiguous floats -> 3x float2 (8B aligned)
            float2* dp = (float2*)(den + (size_t)pix * 6);
            dp[0] = make_float2(f0, f1);
            dp[1] = make_float2(f2, f3);
            dp[2] = make_float2(f4, f5);

            if (e == 0) {
                fa[k][0] = f0; fa[k][1] = f1; fa[k][2] = f2;
                fa[k][3] = f3; fa[k][4] = f4; fa[k][5] = f5;
            } else {
                float d0 = fa[k][0] - f0, d1 = fa[k][1] - f1, d2 = fa[k][2] - f2;
                float d3 = fa[k][3] - f3, d4 = fa[k][4] - f4, d5 = fa[k][5] - f5;
                float o0 = s_B2[0] + s_M[0]*d0 + s_M[1]*d1 + s_M[2]*d2
                                   + s_M[3]*d3 + s_M[4]*d4 + s_M[5]*d5;
                float o1 = s_B2[1] + s_M[6]*d0 + s_M[7]*d1 + s_M[8]*d2
                                   + s_M[9]*d3 + s_M[10]*d4 + s_M[11]*d5;
                ((float2*)outf)[pix] = make_float2(o0, o1);
            }
        }
    }
}

extern "C" void kernel_launch(void* const* d_in, const int* in_sizes, int n_in,
                              void* d_out, int out_size) {
    const float* x   = (const float*)d_in[0];
    const float* x2  = (const float*)d_in[1];
    const float* w1a = (const float*)d_in[2];
    const float* b1a = (const float*)d_in[3];
    const float* w2a = (const float*)d_in[4];
    const float* b2a = (const float*)d_in[5];
    const float* w3a = (const float*)d_in[6];
    const float* b3a = (const float*)d_in[7];
    const float* w1b = (const float*)d_in[8];
    const float* b1b = (const float*)d_in[9];
    const float* w2b = (const float*)d_in[10];
    const float* b2b = (const float*)d_in[11];
    const float* w3b = (const float*)d_in[12];
    const float* b3b = (const float*)d_in[13];
    const float* lw1 = (const float*)d_in[14];
    const float* lb1 = (const float*)d_in[15];
    const float* lw2 = (const float*)d_in[16];
    const float* lb2 = (const float*)d_in[17];

    float* outf = (float*)d_out;                       // [HW, 2]
    float* den1 = (float*)d_out + (size_t)2 * HWdim;   // [H, W, 6]
    float* den2 = (float*)d_out + (size_t)8 * HWdim;   // [H, W, 6]

    fold_mlp_kernel<<<1, 64>>>(lw1, lb1, lw2, lb2);

    dim3 grid(Wdim / TS, Hdim / TS);
    unet_fused_kernel<<<grid, NT>>>(
        x, x2, w1a, b1a, w2a, b2a, w3a, b3a,
        w1b, b1b, w2b, b2b, w3b, b3b,
        outf, den1, den2);
}